// round 15
// baseline (speedup 1.0000x reference)
#include <cuda_runtime.h>
#include <cuda_bf16.h>
#include <cstdint>

// Problem constants (fixed by setup_inputs)
#define BS    16
#define NQ    900
#define NC    151
#define NT    100
#define TT    (BS * NT)      // 1600 total targets
#define NROWS (BS * NQ)      // 14400 query rows
#define NG    (TT / 4)       // 400 target records
#define NITEMS (NG * 4)      // 1600 work items

#define THREADS 256
#define ROWS_PER_BLOCK 16
#define PT_PITCH4 5          // prob table: 5 float4 slots per class

// ---- shared layout (static offsets, bytes) ----
#define SM_REC   0           // 400 * 80B records               32000
#define SM_ROWC  32000       // float4[16] (pcx,pcy,pwx,pwy)      256
#define SM_PA    32256       // float[16] row areas               64
#define SM_PT    32320       // float[151*20]                   12080
#define SM_ID    44400       // int[1600]                        6400
#define SMEM_BYTES 50800

// cost = 5*L1(cxcywh) + (2 - p) - 2*(inter*earea + uni^2)/(uni*earea)
__device__ __forceinline__ float cost_elem(
    float tcx, float tcy, float twx, float twy, float tarea,
    float base,
    float pcx, float pcy, float pwx, float pwy, float parea)
{
    float dcx = pcx - tcx, dcy = pcy - tcy;
    float dwx = pwx - twx, dwy = pwy - twy;
    float sx  = pwx + twx, sy  = pwy + twy;

    float s1 = fabsf(dcx) + fabsf(dcy);
    float s2 = fabsf(dwx) + fabsf(dwy);
    float acc = fmaf(5.0f, s1, fmaf(10.0f, s2, base));

    float mx = fmaxf(fabsf(dcx), fabsf(dwx));
    float my = fmaxf(fabsf(dcy), fabsf(dwy));

    float iw = fmaxf(sx - mx, 0.0f), ih = fmaxf(sy - my, 0.0f);
    float ew = sx + mx,              eh = sy + my;

    float inter = iw * ih;
    float earea = ew * eh;
    float uni   = (parea + tarea) - inter;

    float num = fmaf(uni, uni, inter * earea);
    float q   = __fdividef(num, uni * earea);
    return fmaf(-2.0f, q, acc);
}

extern __shared__ __align__(16) char smem_raw[];

__global__ __launch_bounds__(THREADS, 3)
void matcher_kernel(const float* __restrict__ pred_logits,   // [NROWS, NC]
                    const float* __restrict__ pred_boxes,    // [NROWS, 4]
                    const int*   __restrict__ tgt_labels,    // [TT]
                    const float* __restrict__ tgt_boxes,     // [TT, 4]
                    float*       __restrict__ out)           // [NROWS, TT]
{
    float*  s_rec  = reinterpret_cast<float*>(smem_raw + SM_REC);
    float4* s_rowc = reinterpret_cast<float4*>(smem_raw + SM_ROWC);
    float*  s_pa   = reinterpret_cast<float*>(smem_raw + SM_PA);
    float*  s_pT   = reinterpret_cast<float*>(smem_raw + SM_PT);
    int4*   s_id4  = reinterpret_cast<int4*>(smem_raw + SM_ID);

    const int tid  = threadIdx.x;
    const int lane = tid & 31;
    const int warp = tid >> 5;
    const int row_base = blockIdx.x * ROWS_PER_BLOCK;

    // ---- coalesced register-staged loads of raw targets + ids ----
    const float4* tb4 = reinterpret_cast<const float4*>(tgt_boxes);
    float4 raw[7];
    #pragma unroll
    for (int k = 0; k < 6; k++) raw[k] = tb4[tid + 256 * k];
    if (tid < TT - 1536) raw[6] = tb4[tid + 1536];

    const int4* id4g = reinterpret_cast<const int4*>(tgt_labels);
    int4 idr0 = id4g[tid < NG ? tid : 0];
    int4 idr1 = (tid < NG - 256) ? id4g[tid + 256] : make_int4(0, 0, 0, 0);

    // ---- transformed row constants (16 rows) ----
    if (tid < ROWS_PER_BLOCK) {
        float4 pb = reinterpret_cast<const float4*>(pred_boxes)[row_base + tid];
        s_rowc[tid] = make_float4(pb.x, pb.y, 0.5f * pb.z, 0.5f * pb.w);
        s_pa[tid]   = pb.z * pb.w;
    }

    // ---- softmax: each warp handles rows (warp) and (warp + 8) ----
    #pragma unroll
    for (int half = 0; half < 2; half++) {
        const int r = warp + 8 * half;                 // block-row 0..15
        const float* lg = pred_logits + (row_base + r) * NC;
        float e[5];
        float s = 0.0f;
        #pragma unroll
        for (int k = 0; k < 5; k++) {
            int c = lane + 32 * k;
            e[k] = (c < NC) ? __expf(lg[c]) : 0.0f;
            s += e[k];
        }
        #pragma unroll
        for (int o = 16; o; o >>= 1)
            s += __shfl_xor_sync(0xffffffffu, s, o);
        const float inv = __fdividef(1.0f, s);
        const int grp = r >> 2, sub = r & 3;
        #pragma unroll
        for (int k = 0; k < 5; k++) {
            int c = lane + 32 * k;
            if (c < NC) s_pT[(c * PT_PITCH4 + grp) * 4 + sub] = fmaf(-e[k], inv, 2.0f);
        }
    }

    // ---- in-register transform -> 80B Rec layout in smem ----
    #pragma unroll
    for (int k = 0; k < 6; k++) {
        int i = tid + 256 * k;
        float4 t = raw[k];
        *reinterpret_cast<float4*>(s_rec + 20 * (i >> 2) + 4 * (i & 3)) =
            make_float4(t.x, t.y, 0.5f * t.z, 0.5f * t.w);
        s_rec[20 * (i >> 2) + 16 + (i & 3)] = t.z * t.w;
    }
    if (tid < TT - 1536) {
        int i = tid + 1536;
        float4 t = raw[6];
        *reinterpret_cast<float4*>(s_rec + 20 * (i >> 2) + 4 * (i & 3)) =
            make_float4(t.x, t.y, 0.5f * t.z, 0.5f * t.w);
        s_rec[20 * (i >> 2) + 16 + (i & 3)] = t.z * t.w;
    }
    if (tid < NG) s_id4[tid] = idr0;
    if (tid < NG - 256) s_id4[tid + 256] = idr1;

    __syncthreads();   // probs + recs + ids + row constants visible

    const float4* rec4   = reinterpret_cast<const float4*>(s_rec);
    const float4* probT4 = reinterpret_cast<const float4*>(s_pT);
    float4* out4 = reinterpret_cast<float4*>(out);

    // ---- flattened output loop: item i -> grp = i & 3, gg = i >> 2 ----
    // Lanes within a 4-lane quad share gg -> rec/ids LDS are 4-way broadcast
    // (1 phase instead of 4). grp cycles 0..3 across lanes.
    #pragma unroll 1
    for (int k = 0; k < 7; k++) {
        const int i = tid + 256 * k;
        if (i >= NITEMS) break;
        const int grp = i & 3;           // 0..3
        const int gg  = i >> 2;          // 0..399

        // row constants for this item's grp (register-cached per item)
        float4 RC0 = s_rowc[4 * grp + 0];
        float4 RC1 = s_rowc[4 * grp + 1];
        float4 RC2 = s_rowc[4 * grp + 2];
        float4 RC3 = s_rowc[4 * grp + 3];
        const float4* pa4 = reinterpret_cast<const float4*>(s_pa);
        float4 PA = pa4[grp];
        const float pcx[4] = {RC0.x, RC1.x, RC2.x, RC3.x};
        const float pcy[4] = {RC0.y, RC1.y, RC2.y, RC3.y};
        const float pwx[4] = {RC0.z, RC1.z, RC2.z, RC3.z};
        const float pwy[4] = {RC0.w, RC1.w, RC2.w, RC3.w};
        const float pa [4] = {PA.x,  PA.y,  PA.z,  PA.w};

        float4 T0 = rec4[gg * 5 + 0];    // 4-way broadcast across lanes
        float4 T1 = rec4[gg * 5 + 1];
        float4 T2 = rec4[gg * 5 + 2];
        float4 T3 = rec4[gg * 5 + 3];
        float4 ta = rec4[gg * 5 + 4];
        int4 ids = s_id4[gg];            // broadcast too

        float4 P0 = probT4[ids.x * PT_PITCH4 + grp];
        float4 P1 = probT4[ids.y * PT_PITCH4 + grp];
        float4 P2 = probT4[ids.z * PT_PITCH4 + grp];
        float4 P3 = probT4[ids.w * PT_PITCH4 + grp];
        const float* p0 = reinterpret_cast<const float*>(&P0);
        const float* p1 = reinterpret_cast<const float*>(&P1);
        const float* p2 = reinterpret_cast<const float*>(&P2);
        const float* p3 = reinterpret_cast<const float*>(&P3);

        const int row0 = row_base + 4 * grp;
        #pragma unroll
        for (int r = 0; r < 4; r++) {
            float4 v;
            v.x = cost_elem(T0.x, T0.y, T0.z, T0.w, ta.x, p0[r],
                            pcx[r], pcy[r], pwx[r], pwy[r], pa[r]);
            v.y = cost_elem(T1.x, T1.y, T1.z, T1.w, ta.y, p1[r],
                            pcx[r], pcy[r], pwx[r], pwy[r], pa[r]);
            v.z = cost_elem(T2.x, T2.y, T2.z, T2.w, ta.z, p2[r],
                            pcx[r], pcy[r], pwx[r], pwy[r], pa[r]);
            v.w = cost_elem(T3.x, T3.y, T3.z, T3.w, ta.w, p3[r],
                            pcx[r], pcy[r], pwx[r], pwy[r], pa[r]);
            out4[(row0 + r) * NG + gg] = v;
        }
    }
}

extern "C" void kernel_launch(void* const* d_in, const int* in_sizes, int n_in,
                              void* d_out, int out_size)
{
    const float* pred_logits = (const float*)d_in[0];
    const float* pred_boxes  = (const float*)d_in[1];
    const int*   tgt_labels  = (const int*)  d_in[2];
    const float* tgt_boxes   = (const float*)d_in[3];
    float* out = (float*)d_out;

    cudaFuncSetAttribute(matcher_kernel,
                         cudaFuncAttributeMaxDynamicSharedMemorySize, SMEM_BYTES);
    const int blocks = NROWS / ROWS_PER_BLOCK;   // 900
    matcher_kernel<<<blocks, THREADS, SMEM_BYTES>>>(
        pred_logits, pred_boxes, tgt_labels, tgt_boxes, out);
}

// round 16
// speedup vs baseline: 1.1374x; 1.1374x over previous
#include <cuda_runtime.h>
#include <cuda_bf16.h>
#include <cstdint>

// Problem constants (fixed by setup_inputs)
#define BS    16
#define NQ    900
#define NC    151
#define NT    100
#define TT    (BS * NT)      // 1600 total targets
#define NROWS (BS * NQ)      // 14400 query rows
#define NG    (TT / 4)       // 400 target records
#define NITEMS (NG * 4)      // 1600 work items (4 row-groups x 400 target-groups)

#define THREADS 256
#define ROWS_PER_BLOCK 16
#define PT_PITCH4 5          // prob table: 5 float4 slots per class

// ---- shared layout (static offsets, bytes) ----
#define SM_REC   0           // 400 * 80B records               32000
#define SM_ROWC  32000       // float4[16] (pcx,pcy,pwx,pwy)      256
#define SM_PA    32256       // float[16] row areas               64
#define SM_PT    32320       // float[151*20]                   12080
#define SM_ID    44400       // int[1600]                        6400
#define SMEM_BYTES 50800

// streaming 128-bit store (evict-first; output is write-once)
__device__ __forceinline__ void stg_cs(float4* p, float4 v) {
    asm volatile("st.global.cs.v4.f32 [%0], {%1, %2, %3, %4};"
                 :: "l"(p), "f"(v.x), "f"(v.y), "f"(v.z), "f"(v.w) : "memory");
}

// cost = 5*L1(cxcywh) + (2 - p) - 2*(inter*earea + uni^2)/(uni*earea)
__device__ __forceinline__ float cost_elem(
    float tcx, float tcy, float twx, float twy, float tarea,
    float base,
    float pcx, float pcy, float pwx, float pwy, float parea)
{
    float dcx = pcx - tcx, dcy = pcy - tcy;
    float dwx = pwx - twx, dwy = pwy - twy;
    float sx  = pwx + twx, sy  = pwy + twy;

    float s1 = fabsf(dcx) + fabsf(dcy);
    float s2 = fabsf(dwx) + fabsf(dwy);
    float acc = fmaf(5.0f, s1, fmaf(10.0f, s2, base));

    float mx = fmaxf(fabsf(dcx), fabsf(dwx));
    float my = fmaxf(fabsf(dcy), fabsf(dwy));

    float iw = fmaxf(sx - mx, 0.0f), ih = fmaxf(sy - my, 0.0f);
    float ew = sx + mx,              eh = sy + my;

    float inter = iw * ih;
    float earea = ew * eh;
    float uni   = (parea + tarea) - inter;

    float num = fmaf(uni, uni, inter * earea);
    float q   = __fdividef(num, uni * earea);
    return fmaf(-2.0f, q, acc);
}

extern __shared__ __align__(16) char smem_raw[];

__global__ __launch_bounds__(THREADS, 3)
void matcher_kernel(const float* __restrict__ pred_logits,   // [NROWS, NC]
                    const float* __restrict__ pred_boxes,    // [NROWS, 4]
                    const int*   __restrict__ tgt_labels,    // [TT]
                    const float* __restrict__ tgt_boxes,     // [TT, 4]
                    float*       __restrict__ out)           // [NROWS, TT]
{
    float*  s_rec  = reinterpret_cast<float*>(smem_raw + SM_REC);
    float4* s_rowc = reinterpret_cast<float4*>(smem_raw + SM_ROWC);
    float*  s_pa   = reinterpret_cast<float*>(smem_raw + SM_PA);
    float*  s_pT   = reinterpret_cast<float*>(smem_raw + SM_PT);
    int4*   s_id4  = reinterpret_cast<int4*>(smem_raw + SM_ID);

    const int tid  = threadIdx.x;
    const int lane = tid & 31;
    const int warp = tid >> 5;
    const int row_base = blockIdx.x * ROWS_PER_BLOCK;

    // ---- coalesced register-staged loads of raw targets + ids ----
    const float4* tb4 = reinterpret_cast<const float4*>(tgt_boxes);
    float4 raw[7];
    #pragma unroll
    for (int k = 0; k < 6; k++) raw[k] = tb4[tid + 256 * k];
    if (tid < TT - 1536) raw[6] = tb4[tid + 1536];

    const int4* id4g = reinterpret_cast<const int4*>(tgt_labels);
    int4 idr0 = id4g[tid < NG ? tid : 0];
    int4 idr1 = (tid < NG - 256) ? id4g[tid + 256] : make_int4(0, 0, 0, 0);

    // ---- transformed row constants (16 rows) ----
    if (tid < ROWS_PER_BLOCK) {
        float4 pb = reinterpret_cast<const float4*>(pred_boxes)[row_base + tid];
        s_rowc[tid] = make_float4(pb.x, pb.y, 0.5f * pb.z, 0.5f * pb.w);
        s_pa[tid]   = pb.z * pb.w;
    }

    // ---- softmax: each warp handles rows (warp) and (warp + 8) ----
    #pragma unroll
    for (int half = 0; half < 2; half++) {
        const int r = warp + 8 * half;                 // block-row 0..15
        const float* lg = pred_logits + (row_base + r) * NC;
        float e[5];
        float s = 0.0f;
        #pragma unroll
        for (int k = 0; k < 5; k++) {
            int c = lane + 32 * k;
            e[k] = (c < NC) ? __expf(lg[c]) : 0.0f;
            s += e[k];
        }
        #pragma unroll
        for (int o = 16; o; o >>= 1)
            s += __shfl_xor_sync(0xffffffffu, s, o);
        const float inv = __fdividef(1.0f, s);
        const int grp = r >> 2, sub = r & 3;
        #pragma unroll
        for (int k = 0; k < 5; k++) {
            int c = lane + 32 * k;
            if (c < NC) s_pT[(c * PT_PITCH4 + grp) * 4 + sub] = fmaf(-e[k], inv, 2.0f);
        }
    }

    // ---- in-register transform -> 80B Rec layout in smem ----
    #pragma unroll
    for (int k = 0; k < 6; k++) {
        int i = tid + 256 * k;
        float4 t = raw[k];
        *reinterpret_cast<float4*>(s_rec + 20 * (i >> 2) + 4 * (i & 3)) =
            make_float4(t.x, t.y, 0.5f * t.z, 0.5f * t.w);
        s_rec[20 * (i >> 2) + 16 + (i & 3)] = t.z * t.w;
    }
    if (tid < TT - 1536) {
        int i = tid + 1536;
        float4 t = raw[6];
        *reinterpret_cast<float4*>(s_rec + 20 * (i >> 2) + 4 * (i & 3)) =
            make_float4(t.x, t.y, 0.5f * t.z, 0.5f * t.w);
        s_rec[20 * (i >> 2) + 16 + (i & 3)] = t.z * t.w;
    }
    if (tid < NG) s_id4[tid] = idr0;
    if (tid < NG - 256) s_id4[tid + 256] = idr1;

    __syncthreads();   // probs + recs + ids + row constants visible

    const float4* rec4   = reinterpret_cast<const float4*>(s_rec);
    const float4* probT4 = reinterpret_cast<const float4*>(s_pT);
    const float4* pa4    = reinterpret_cast<const float4*>(s_pa);
    float4* out4 = reinterpret_cast<float4*>(out);

    // ---- flattened output loop: item i = grp*400 + gg ----
    // Incremental grp/gg tracking (stride 256 < 400 -> at most one wrap/step).
    int grp = tid / NG;            // tid < 1600 always, grp in {0}
    int gg  = tid - grp * NG;
    #pragma unroll 1
    for (int k = 0; k < 7; k++) {
        const int i = tid + 256 * k;
        if (i >= NITEMS) break;

        float4 RC0 = s_rowc[4 * grp + 0];
        float4 RC1 = s_rowc[4 * grp + 1];
        float4 RC2 = s_rowc[4 * grp + 2];
        float4 RC3 = s_rowc[4 * grp + 3];
        float4 PA  = pa4[grp];
        const float pcx[4] = {RC0.x, RC1.x, RC2.x, RC3.x};
        const float pcy[4] = {RC0.y, RC1.y, RC2.y, RC3.y};
        const float pwx[4] = {RC0.z, RC1.z, RC2.z, RC3.z};
        const float pwy[4] = {RC0.w, RC1.w, RC2.w, RC3.w};
        const float pa [4] = {PA.x,  PA.y,  PA.z,  PA.w};

        float4 T0 = rec4[gg * 5 + 0];
        float4 T1 = rec4[gg * 5 + 1];
        float4 T2 = rec4[gg * 5 + 2];
        float4 T3 = rec4[gg * 5 + 3];
        float4 ta = rec4[gg * 5 + 4];
        int4 ids = s_id4[gg];

        float4 P0 = probT4[ids.x * PT_PITCH4 + grp];
        float4 P1 = probT4[ids.y * PT_PITCH4 + grp];
        float4 P2 = probT4[ids.z * PT_PITCH4 + grp];
        float4 P3 = probT4[ids.w * PT_PITCH4 + grp];
        const float* p0 = reinterpret_cast<const float*>(&P0);
        const float* p1 = reinterpret_cast<const float*>(&P1);
        const float* p2 = reinterpret_cast<const float*>(&P2);
        const float* p3 = reinterpret_cast<const float*>(&P3);

        const int row0 = row_base + 4 * grp;
        #pragma unroll
        for (int r = 0; r < 4; r++) {
            float4 v;
            v.x = cost_elem(T0.x, T0.y, T0.z, T0.w, ta.x, p0[r],
                            pcx[r], pcy[r], pwx[r], pwy[r], pa[r]);
            v.y = cost_elem(T1.x, T1.y, T1.z, T1.w, ta.y, p1[r],
                            pcx[r], pcy[r], pwx[r], pwy[r], pa[r]);
            v.z = cost_elem(T2.x, T2.y, T2.z, T2.w, ta.z, p2[r],
                            pcx[r], pcy[r], pwx[r], pwy[r], pa[r]);
            v.w = cost_elem(T3.x, T3.y, T3.z, T3.w, ta.w, p3[r],
                            pcx[r], pcy[r], pwx[r], pwy[r], pa[r]);
            stg_cs(&out4[(row0 + r) * NG + gg], v);   // streaming store
        }

        // advance item index: gg += 256 with single-wrap correction
        gg += 256;
        if (gg >= NG) { gg -= NG; grp += 1; }
    }
}

extern "C" void kernel_launch(void* const* d_in, const int* in_sizes, int n_in,
                              void* d_out, int out_size)
{
    const float* pred_logits = (const float*)d_in[0];
    const float* pred_boxes  = (const float*)d_in[1];
    const int*   tgt_labels  = (const int*)  d_in[2];
    const float* tgt_boxes   = (const float*)d_in[3];
    float* out = (float*)d_out;

    cudaFuncSetAttribute(matcher_kernel,
                         cudaFuncAttributeMaxDynamicSharedMemorySize, SMEM_BYTES);
    const int blocks = NROWS / ROWS_PER_BLOCK;   // 900
    matcher_kernel<<<blocks, THREADS, SMEM_BYTES>>>(
        pred_logits, pred_boxes, tgt_labels, tgt_boxes, out);
}